// round 8
// baseline (speedup 1.0000x reference)
#include <cuda_runtime.h>
#include <cuda_fp16.h>
#include <mma.h>
#include <cstdint>
#include <math.h>

using namespace nvcuda;

#define BB 1024
#define TT 100
#define HH 256
#define H2 512
#define LDW 264          // resident W smem lead dim (fp16 elems)
#define LDA 264          // A smem lead dim (fp16 elems)
#define LDC 132          // epilogue C lead dim (f32)
#define LDG2 48          // big-GEMM chunk lead dim

// ---------------- device scratch ----------------
__device__ float d_m[BB];
__device__ float d_h1[2][2][BB*HH];    // masked h, fp32
__device__ float d_h2[2][2][BB*HH];
__device__ float d_p2[TT][BB][H2];
__device__ __half d_W1[2][1024*256];      // layer1 Whh, fp16, r'=4h+g
__device__ __half d_Whh2[2][1024*256];    // layer2 Whh, fp16
__device__ __half d_Wih2hi[2048*512];     // layer2 Wih hi/lo fp16, n=dir*1024+r'
__device__ __half d_Wih2lo[2048*512];
__device__ float d_bx1[2][1024];
__device__ float d_bx2[2][1024];
__device__ float d_wix[2][1024*2];
__device__ __half d_A2[(size_t)TT*BB*512];    // p1*mask2, fp16
__device__ __half d_Z2[(size_t)TT*BB*2048];   // layer-2 input projection, fp16
__device__ int d_bar[2][16];

__device__ __forceinline__ float sigf(float x){ return 1.0f/(1.0f+__expf(-x)); }

// ---------------- mean ----------------
__global__ void mean_kernel(const float* __restrict__ x0){
    int b = blockIdx.x*blockDim.x + threadIdx.x;
    if (b < BB){
        float s = 0.f;
        #pragma unroll 4
        for (int t=0; t<TT; t++) s += x0[b*TT+t];
        d_m[b] = s*(1.0f/TT);
    }
}

// ---------------- zero states + barriers ----------------
__global__ void zero_kernel(){
    int i = blockIdx.x*blockDim.x + threadIdx.x;
    if (i < BB*HH){
        d_h1[0][0][i]=0.f; d_h1[0][1][i]=0.f;
        d_h2[0][0][i]=0.f; d_h2[0][1][i]=0.f;
    }
    if (i < 16){ d_bar[0][i]=0; d_bar[1][i]=0; }
}

// ---------------- weight prep ----------------
__global__ void prep_weights(
    const float* __restrict__ Whh1f, const float* __restrict__ Whh1b,
    const float* __restrict__ Wih2f, const float* __restrict__ Whh2f,
    const float* __restrict__ Wih2b, const float* __restrict__ Whh2b,
    const float* __restrict__ Wih1f, const float* __restrict__ Wih1b,
    const float* __restrict__ bih1f, const float* __restrict__ bhh1f,
    const float* __restrict__ bih1b, const float* __restrict__ bhh1b,
    const float* __restrict__ bih2f, const float* __restrict__ bhh2f,
    const float* __restrict__ bih2b, const float* __restrict__ bhh2b)
{
    int stride = gridDim.x*blockDim.x;
    int idx = blockIdx.x*blockDim.x + threadIdx.x;
    for (int i = idx; i < 2*1024*256; i += stride){
        int dir = i/(1024*256); int r = (i/256)%1024; int k = i%256;
        int h = r>>2, g = r&3;
        const float* W1 = dir ? Whh1b : Whh1f;
        const float* W2 = dir ? Whh2b : Whh2f;
        d_W1[dir][r*256+k]   = __float2half_rn(W1[(g*256+h)*256 + k]);
        d_Whh2[dir][r*256+k] = __float2half_rn(W2[(g*256+h)*256 + k]);
    }
    for (int i = idx; i < 2048*512; i += stride){
        int n = i>>9, k = i&511;
        int dir = n>>10, r = n&1023;
        int h = r>>2, g = r&3;
        const float* W = dir ? Wih2b : Wih2f;
        float w = W[(g*256+h)*512 + k];
        __half hi = __float2half_rn(w);
        __half lo = __float2half_rn(w - __half2float(hi));
        d_Wih2hi[i] = hi;
        d_Wih2lo[i] = lo;
    }
    for (int i = idx; i < 2*1024; i += stride){
        int dir = i>>10; int r = i&1023;
        int h = r>>2, g = r&3;
        const float* b1i = dir ? bih1b : bih1f; const float* b1h = dir ? bhh1b : bhh1f;
        const float* b2i = dir ? bih2b : bih2f; const float* b2h = dir ? bhh2b : bhh2f;
        d_bx1[dir][r] = b1i[g*256+h] + b1h[g*256+h];
        d_bx2[dir][r] = b2i[g*256+h] + b2h[g*256+h];
        const float* Wi = dir ? Wih1b : Wih1f;
        d_wix[dir][r*2+0] = Wi[(g*256+h)*2 + 0];
        d_wix[dir][r*2+1] = Wi[(g*256+h)*2 + 1];
    }
}

// ---------------- persistent recurrent LSTM ----------------
// grid (8 ntile, 8 btile, 2 dir) = 128 CTAs. W fp16 resident; A staged full-K
// per step split hi/lo fp16 (2-pass compensated MMA); c in registers;
// group barrier per step.
#define WBYTES (128*LDW*2)                   // 67584
#define PERSIST_SMEM (2048 + 3*WBYTES)       // 204800

template<int LAYER>
__global__ void __launch_bounds__(256,1) lstm_persist(
    const float* __restrict__ x0,
    const float* __restrict__ mrec,     // mask1 (L1) / mask3 (L2)
    const float* __restrict__ mask2)    // L1 only
{
    extern __shared__ char sm[];
    float* sBias = (float*)sm;
    float* sWix  = (float*)(sm + 512);
    __half* sW  = (__half*)(sm + 2048);
    __half* sAh = (__half*)(sm + 2048 + WBYTES);
    __half* sAl = (__half*)(sm + 2048 + 2*WBYTES);
    float* sC = (float*)sAh;            // alias: C written after MMAs done

    const int tid = threadIdx.x, wid = tid>>5;
    const int ntile = blockIdx.x, btile = blockIdx.y, dir = blockIdx.z;
    const int gr0 = ntile*128;
    int* ctr = &d_bar[LAYER-1][dir*8 + btile];

    const __half* Wsrc; const float* bx; float *hp0, *hp1;
    if (LAYER==1){ Wsrc=d_W1[dir];   bx=d_bx1[dir]; hp0=d_h1[0][dir]; hp1=d_h1[1][dir]; }
    else         { Wsrc=d_Whh2[dir]; bx=d_bx2[dir]; hp0=d_h2[0][dir]; hp1=d_h2[1][dir]; }

    #pragma unroll
    for (int it=0; it<16; it++){
        int lin = tid + it*256; int r = lin>>5, seg = lin&31;
        *(uint4*)(sW + r*LDW + seg*8) = *(const uint4*)(Wsrc + (gr0+r)*256 + seg*8);
    }
    if (tid < 128) sBias[tid] = bx[gr0 + tid];
    if (LAYER==1) sWix[tid] = d_wix[dir][gr0*2 + tid];
    __syncthreads();

    const int wm = (wid&3)*32, wn = (wid>>2)*64;
    const int row = tid>>1, half = tid&1;
    const int bE = btile*128 + row;

    float creg[16];
    #pragma unroll
    for (int i=0;i<16;i++) creg[i]=0.f;

    for (int t=0; t<TT; t++){
        const int tin = dir ? (TT-1-t) : t;
        const float* h_in = (t&1) ? hp1 : hp0;
        float* h_out = (t&1) ? hp0 : hp1;

        wmma::fragment<wmma::accumulator,16,16,16,float> acc[2][4];
        #pragma unroll
        for (int i=0;i<2;i++)
            #pragma unroll
            for (int j=0;j<4;j++) wmma::fill_fragment(acc[i][j], 0.f);

        if (t > 0){
            // ---- stage full-K A, split fp16 hi/lo (h already masked) ----
            const float* src = h_in + (size_t)bE*HH + half*128;
            __half* dh = sAh + row*LDA + half*128;
            __half* dl = sAl + row*LDA + half*128;
            #pragma unroll
            for (int i=0;i<16;i++){
                float4 a = __ldcg((const float4*)(src + i*8));
                float4 b = __ldcg((const float4*)(src + i*8 + 4));
                float v[8] = {a.x,a.y,a.z,a.w,b.x,b.y,b.z,b.w};
                uint4 uh, ul;
                __half* hp = (__half*)&uh;
                __half* lp = (__half*)&ul;
                #pragma unroll
                for (int j=0;j<8;j++){
                    __half hv = __float2half_rn(v[j]);
                    hp[j] = hv;
                    lp[j] = __float2half_rn(v[j] - __half2float(hv));
                }
                *(uint4*)(dh + i*8) = uh;
                *(uint4*)(dl + i*8) = ul;
            }
            __syncthreads();
            // ---- MMA: 16 k-slices, no internal syncs, 2 passes ----
            #pragma unroll
            for (int k16=0; k16<16; k16++){
                wmma::fragment<wmma::matrix_a,16,16,16,__half,wmma::row_major> fah[2], fal[2];
                #pragma unroll
                for (int i=0;i<2;i++){
                    wmma::load_matrix_sync(fah[i], sAh + (wm+16*i)*LDA + k16*16, LDA);
                    wmma::load_matrix_sync(fal[i], sAl + (wm+16*i)*LDA + k16*16, LDA);
                }
                #pragma unroll
                for (int j=0;j<4;j++){
                    wmma::fragment<wmma::matrix_b,16,16,16,__half,wmma::col_major> fb;
                    wmma::load_matrix_sync(fb, sW + (wn+16*j)*LDW + k16*16, LDW);
                    #pragma unroll
                    for (int i=0;i<2;i++){
                        wmma::mma_sync(acc[i][j], fah[i], fb, acc[i][j]);
                        wmma::mma_sync(acc[i][j], fal[i], fb, acc[i][j]);
                    }
                }
            }
            __syncthreads();   // all warps done reading sAh before C aliases it
        }

        // ---- dump C ----
        #pragma unroll
        for (int i=0;i<2;i++)
            #pragma unroll
            for (int j=0;j<4;j++)
                wmma::store_matrix_sync(sC + (wm+16*i)*LDC + wn + 16*j, acc[i][j],
                                        LDC, wmma::mem_row_major);
        __syncthreads();

        // ---- LSTM cell epilogue ----
        float xv = 0.f, mb = 0.f;
        if (LAYER==1){ mb = d_m[bE]; xv = x0[bE*TT + tin] - mb; }
        __half2 zv[32];
        if (LAYER==2){
            const __half2* zp = (const __half2*)(d_Z2 + ((size_t)tin*BB + bE)*2048
                                                 + dir*1024 + gr0 + half*64);
            #pragma unroll
            for (int j=0;j<32;j++) zv[j] = zp[j];
        }
        const float* cr = sC + row*LDC + half*64;
        const float* mr = mrec + (size_t)bE*HH + ntile*32 + half*16;
        #pragma unroll
        for (int hh=0; hh<16; hh++){
            int rl = half*64 + hh*4;
            float g0 = cr[hh*4+0] + sBias[rl+0];
            float g1 = cr[hh*4+1] + sBias[rl+1];
            float g2 = cr[hh*4+2] + sBias[rl+2];
            float g3 = cr[hh*4+3] + sBias[rl+3];
            if (LAYER==1){
                g0 += sWix[(rl+0)*2]*xv + sWix[(rl+0)*2+1]*mb;
                g1 += sWix[(rl+1)*2]*xv + sWix[(rl+1)*2+1]*mb;
                g2 += sWix[(rl+2)*2]*xv + sWix[(rl+2)*2+1]*mb;
                g3 += sWix[(rl+3)*2]*xv + sWix[(rl+3)*2+1]*mb;
            } else {
                g0 += __low2float(zv[hh*2]);   g1 += __high2float(zv[hh*2]);
                g2 += __low2float(zv[hh*2+1]); g3 += __high2float(zv[hh*2+1]);
            }
            float ig = sigf(g0), fg = sigf(g1), gt = tanhf(g2), og = sigf(g3);
            float cn = fg*creg[hh] + ig*gt;
            float hn = og*tanhf(cn);
            creg[hh] = cn;
            int hglob = ntile*32 + half*16 + hh;
            h_out[(size_t)bE*HH + hglob] = hn * mr[hh];     // pre-masked for recurrence
            if (LAYER==1){
                d_A2[((size_t)t*BB + bE)*512 + dir*HH + hglob] =
                    __float2half_rn(hn * mask2[(size_t)bE*H2 + dir*HH + hglob]);
            } else {
                d_p2[t][bE][dir*HH + hglob] = hn;
            }
        }

        // ---- group barrier (8 ntile CTAs per (btile,dir)) ----
        if (t < TT-1){
            __threadfence();
            __syncthreads();
            if (tid == 0){
                atomicAdd(ctr, 1);
                int target = 8*(t+1);
                while (__ldcg((const int*)ctr) < target) __nanosleep(20);
            }
            __syncthreads();
        }
    }
}

// ---------------- big GEMM: Z2 = A2 @ Wih2^T (2-pass: A*(Wh) + A*(Wl)) ----------
#define SETSZ (3*128*LDG2)
#define GEMM_SMEM (2*SETSZ*2)    // 73728

__global__ void __launch_bounds__(256,2) gemm_z2(){
    extern __shared__ char sm[];
    __half* buf = (__half*)sm;
    float* sC = (float*)sm;
    const int tid = threadIdx.x, wid = tid>>5;
    const int n0 = blockIdx.x*128;
    const int m0 = blockIdx.y*128;
    const int wm = (wid&3)*32, wn = (wid>>2)*64;

    wmma::fragment<wmma::accumulator,16,16,16,float> acc[2][4];
    #pragma unroll
    for (int i=0;i<2;i++)
        #pragma unroll
        for (int j=0;j<4;j++) wmma::fill_fragment(acc[i][j], 0.f);

    // stage chunk 0
    #pragma unroll
    for (int it=0; it<2; it++){
        int lin = tid + it*256; int r = lin>>2, seg = lin&3;
        *(uint4*)(buf + r*LDG2 + seg*8)             = *(const uint4*)(d_A2 + (size_t)(m0+r)*512 + seg*8);
        *(uint4*)(buf + 128*LDG2 + r*LDG2 + seg*8)  = *(const uint4*)(d_Wih2hi + (size_t)(n0+r)*512 + seg*8);
        *(uint4*)(buf + 2*128*LDG2 + r*LDG2 + seg*8)= *(const uint4*)(d_Wih2lo + (size_t)(n0+r)*512 + seg*8);
    }
    __syncthreads();

    for (int kc=0; kc<16; kc++){
        uint4 v[6];
        if (kc < 15){
            #pragma unroll
            for (int it=0; it<2; it++){
                int lin = tid + it*256; int r = lin>>2, seg = lin&3;
                size_t ka = (size_t)(m0+r)*512 + (kc+1)*32 + seg*8;
                size_t kw = (size_t)(n0+r)*512 + (kc+1)*32 + seg*8;
                v[it*3+0] = *(const uint4*)(d_A2 + ka);
                v[it*3+1] = *(const uint4*)(d_Wih2hi + kw);
                v[it*3+2] = *(const uint4*)(d_Wih2lo + kw);
            }
        }
        {
            const __half* p = buf + (kc&1)*SETSZ;
            #pragma unroll
            for (int k16=0; k16<2; k16++){
                wmma::fragment<wmma::matrix_a,16,16,16,__half,wmma::row_major> fa[2];
                #pragma unroll
                for (int i=0;i<2;i++)
                    wmma::load_matrix_sync(fa[i], p + (wm+16*i)*LDG2 + k16*16, LDG2);
                #pragma unroll
                for (int j=0;j<4;j++){
                    wmma::fragment<wmma::matrix_b,16,16,16,__half,wmma::col_major> fbh, fbl;
                    wmma::load_matrix_sync(fbh, p + 128*LDG2 + (wn+16*j)*LDG2 + k16*16, LDG2);
                    wmma::load_matrix_sync(fbl, p + 2*128*LDG2 + (wn+16*j)*LDG2 + k16*16, LDG2);
                    #pragma unroll
                    for (int i=0;i<2;i++){
                        wmma::mma_sync(acc[i][j], fa[i], fbh, acc[i][j]);
                        wmma::mma_sync(acc[i][j], fa[i], fbl, acc[i][j]);
                    }
                }
            }
        }
        if (kc < 15){
            __half* q = buf + ((kc+1)&1)*SETSZ;
            #pragma unroll
            for (int it=0; it<2; it++){
                int lin = tid + it*256; int r = lin>>2, seg = lin&3;
                *(uint4*)(q + r*LDG2 + seg*8)              = v[it*3+0];
                *(uint4*)(q + 128*LDG2 + r*LDG2 + seg*8)   = v[it*3+1];
                *(uint4*)(q + 2*128*LDG2 + r*LDG2 + seg*8) = v[it*3+2];
            }
        }
        __syncthreads();
    }

    // epilogue: fp16 Z2 out
    #pragma unroll
    for (int i=0;i<2;i++)
        #pragma unroll
        for (int j=0;j<4;j++)
            wmma::store_matrix_sync(sC + (wm+16*i)*LDC + wn + 16*j, acc[i][j],
                                    LDC, wmma::mem_row_major);
    __syncthreads();
    const int row = tid>>1, half = tid&1;
    __half2* zp = (__half2*)(d_Z2 + (size_t)(m0+row)*2048 + n0 + half*64);
    const float* cr = sC + row*LDC + half*64;
    #pragma unroll
    for (int j=0;j<32;j++)
        zp[j] = __floats2half2_rn(cr[2*j], cr[2*j+1]);
}

// ---------------- output projection ----------------
__global__ void proj_kernel(const float* __restrict__ Wout,
                            const float* __restrict__ bout,
                            const float* __restrict__ mask4,
                            float* __restrict__ out)
{
    int w = blockIdx.x*(blockDim.x>>5) + (threadIdx.x>>5);
    int lane = threadIdx.x & 31;
    if (w >= BB*TT) return;
    int b = w/TT, t = w%TT;
    float s = 0.f;
    #pragma unroll
    for (int j = lane; j < H2; j += 32)
        s += d_p2[t][b][j] * mask4[b*H2 + j] * Wout[j];
    #pragma unroll
    for (int o = 16; o > 0; o >>= 1) s += __shfl_xor_sync(0xffffffffu, s, o);
    if (lane == 0) out[b*TT + t] = s + bout[0] + d_m[b];
}

// ---------------- launcher ----------------
extern "C" void kernel_launch(void* const* d_in, const int* in_sizes, int n_in,
                              void* d_out, int out_size)
{
    const float* x0    = (const float*)d_in[0];
    const float* Wih1f = (const float*)d_in[1];
    const float* Whh1f = (const float*)d_in[2];
    const float* bih1f = (const float*)d_in[3];
    const float* bhh1f = (const float*)d_in[4];
    const float* Wih1b = (const float*)d_in[5];
    const float* Whh1b = (const float*)d_in[6];
    const float* bih1b = (const float*)d_in[7];
    const float* bhh1b = (const float*)d_in[8];
    const float* Wih2f = (const float*)d_in[9];
    const float* Whh2f = (const float*)d_in[10];
    const float* bih2f = (const float*)d_in[11];
    const float* bhh2f = (const float*)d_in[12];
    const float* Wih2b = (const float*)d_in[13];
    const float* Whh2b = (const float*)d_in[14];
    const float* bih2b = (const float*)d_in[15];
    const float* bhh2b = (const float*)d_in[16];
    const float* Wout  = (const float*)d_in[17];
    const float* bout  = (const float*)d_in[18];
    const float* mask1 = (const float*)d_in[19];
    const float* mask2 = (const float*)d_in[20];
    const float* mask3 = (const float*)d_in[21];
    const float* mask4 = (const float*)d_in[22];
    float* out = (float*)d_out;

    cudaFuncSetAttribute(lstm_persist<1>, cudaFuncAttributeMaxDynamicSharedMemorySize, PERSIST_SMEM);
    cudaFuncSetAttribute(lstm_persist<2>, cudaFuncAttributeMaxDynamicSharedMemorySize, PERSIST_SMEM);
    cudaFuncSetAttribute(gemm_z2, cudaFuncAttributeMaxDynamicSharedMemorySize, GEMM_SMEM);

    mean_kernel<<<(BB+255)/256, 256>>>(x0);
    zero_kernel<<<(BB*HH+255)/256, 256>>>();
    prep_weights<<<1024, 256>>>(Whh1f, Whh1b, Wih2f, Whh2f, Wih2b, Whh2b,
                                Wih1f, Wih1b,
                                bih1f, bhh1f, bih1b, bhh1b,
                                bih2f, bhh2f, bih2b, bhh2b);

    lstm_persist<1><<<dim3(8,8,2), 256, PERSIST_SMEM>>>(x0, mask1, mask2);
    gemm_z2<<<dim3(16,800), 256, GEMM_SMEM>>>();
    lstm_persist<2><<<dim3(8,8,2), 256, PERSIST_SMEM>>>(nullptr, mask3, nullptr);

    proj_kernel<<<(BB*TT+7)/8, 256>>>(Wout, bout, mask4, out);
}

// round 9
// speedup vs baseline: 1.6306x; 1.6306x over previous
#include <cuda_runtime.h>
#include <cuda_fp16.h>
#include <mma.h>
#include <cstdint>
#include <math.h>

using namespace nvcuda;

#define BB 1024
#define TT 100
#define HH 256
#define H2 512
#define LDW 264          // resident W smem lead dim (fp16 elems)
#define LDAC 72          // A chunk smem lead dim (fp16 elems)
#define LDC 132          // epilogue C lead dim (f32)
#define LDG2 48          // big-GEMM chunk lead dim

// ---------------- device scratch ----------------
__device__ float d_m[BB];
__device__ __half d_hh[2][2][2][BB*HH];   // [layer][ping][dir] masked h, fp16 HI
__device__ __half d_hl[2][2][2][BB*HH];   // fp16 LO
__device__ float d_p2[TT][BB][H2];
__device__ __half d_W1[2][1024*256];      // layer1 Whh fp16, r'=4h+g
__device__ __half d_Whh2[2][1024*256];
__device__ __half d_Wih2hi[2048*512];
__device__ __half d_Wih2lo[2048*512];
__device__ float d_bx1[2][1024];
__device__ float d_bx2[2][1024];
__device__ float d_wix[2][1024*2];
__device__ __half d_A2[(size_t)TT*BB*512];
__device__ __half d_Z2[(size_t)TT*BB*2048];
__device__ int d_bar[2][16];

__device__ __forceinline__ float sigf(float x){ return 1.0f/(1.0f+__expf(-x)); }

#define CP16(s,g) asm volatile("cp.async.cg.shared.global [%0], [%1], 16;"::"r"(s),"l"(g):"memory")
#define CP_COMMIT() asm volatile("cp.async.commit_group;":::"memory")
#define CP_WAIT(n) asm volatile("cp.async.wait_group %0;"::"n"(n):"memory")

__device__ __forceinline__ uint32_t smem_u32(const void* p){
    uint32_t a;
    asm("{ .reg .u64 t; cvta.to.shared.u64 t, %1; cvt.u32.u64 %0, t; }":"=r"(a):"l"(p));
    return a;
}

// ---------------- mean ----------------
__global__ void mean_kernel(const float* __restrict__ x0){
    int b = blockIdx.x*blockDim.x + threadIdx.x;
    if (b < BB){
        float s = 0.f;
        #pragma unroll 4
        for (int t=0; t<TT; t++) s += x0[b*TT+t];
        d_m[b] = s*(1.0f/TT);
    }
}

// ---------------- zero barriers ----------------
__global__ void zero_kernel(){
    int i = blockIdx.x*blockDim.x + threadIdx.x;
    if (i < 16){ d_bar[0][i]=0; d_bar[1][i]=0; }
}

// ---------------- weight prep ----------------
__global__ void prep_weights(
    const float* __restrict__ Whh1f, const float* __restrict__ Whh1b,
    const float* __restrict__ Wih2f, const float* __restrict__ Whh2f,
    const float* __restrict__ Wih2b, const float* __restrict__ Whh2b,
    const float* __restrict__ Wih1f, const float* __restrict__ Wih1b,
    const float* __restrict__ bih1f, const float* __restrict__ bhh1f,
    const float* __restrict__ bih1b, const float* __restrict__ bhh1b,
    const float* __restrict__ bih2f, const float* __restrict__ bhh2f,
    const float* __restrict__ bih2b, const float* __restrict__ bhh2b)
{
    int stride = gridDim.x*blockDim.x;
    int idx = blockIdx.x*blockDim.x + threadIdx.x;
    for (int i = idx; i < 2*1024*256; i += stride){
        int dir = i/(1024*256); int r = (i/256)%1024; int k = i%256;
        int h = r>>2, g = r&3;
        const float* W1 = dir ? Whh1b : Whh1f;
        const float* W2 = dir ? Whh2b : Whh2f;
        d_W1[dir][r*256+k]   = __float2half_rn(W1[(g*256+h)*256 + k]);
        d_Whh2[dir][r*256+k] = __float2half_rn(W2[(g*256+h)*256 + k]);
    }
    for (int i = idx; i < 2048*512; i += stride){
        int n = i>>9, k = i&511;
        int dir = n>>10, r = n&1023;
        int h = r>>2, g = r&3;
        const float* W = dir ? Wih2b : Wih2f;
        float w = W[(g*256+h)*512 + k];
        __half hi = __float2half_rn(w);
        d_Wih2hi[i] = hi;
        d_Wih2lo[i] = __float2half_rn(w - __half2float(hi));
    }
    for (int i = idx; i < 2*1024; i += stride){
        int dir = i>>10; int r = i&1023;
        int h = r>>2, g = r&3;
        const float* b1i = dir ? bih1b : bih1f; const float* b1h = dir ? bhh1b : bhh1f;
        const float* b2i = dir ? bih2b : bih2f; const float* b2h = dir ? bhh2b : bhh2f;
        d_bx1[dir][r] = b1i[g*256+h] + b1h[g*256+h];
        d_bx2[dir][r] = b2i[g*256+h] + b2h[g*256+h];
        const float* Wi = dir ? Wih1b : Wih1f;
        d_wix[dir][r*2+0] = Wi[(g*256+h)*2 + 0];
        d_wix[dir][r*2+1] = Wi[(g*256+h)*2 + 1];
    }
}

// ---------------- persistent recurrent LSTM ----------------
// grid (8 ntile, 8 btile, 2 dir) = 128 CTAs. W fp16 resident.
// h stored pre-masked + pre-split hi/lo fp16 -> staging is pure cp.async copy,
// 4 chunk-groups pipelined against the MMA loop. c in registers.
#define WBYTES (128*LDW*2)          // 67584
#define CHUNKB (128*LDAC*2)         // 18432 (one of hi/lo)
#define CHUNK_TOT (2*CHUNKB)        // 36864
#define OFF_A (2048 + WBYTES)       // 69632
#define PERSIST_SMEM (OFF_A + 4*CHUNK_TOT)   // 217088

template<int LAYER>
__global__ void __launch_bounds__(256,1) lstm_persist(
    const float* __restrict__ x0,
    const float* __restrict__ mrec,     // mask1 (L1) / mask3 (L2)
    const float* __restrict__ mask2)    // L1 only
{
    extern __shared__ char sm[];
    float* sBias = (float*)sm;
    float* sWix  = (float*)(sm + 512);
    __half* sW  = (__half*)(sm + 2048);
    float* sC = (float*)(sm + OFF_A);
    const uint32_t saddrA = smem_u32(sm) + OFF_A;

    const int tid = threadIdx.x, wid = tid>>5;
    const int ntile = blockIdx.x, btile = blockIdx.y, dir = blockIdx.z;
    const int gr0 = ntile*128;
    int* ctr = &d_bar[LAYER-1][dir*8 + btile];

    const __half* Wsrc; const float* bx;
    __half *h0h = d_hh[LAYER-1][0][dir], *h1h = d_hh[LAYER-1][1][dir];
    __half *h0l = d_hl[LAYER-1][0][dir], *h1l = d_hl[LAYER-1][1][dir];
    if (LAYER==1){ Wsrc=d_W1[dir];   bx=d_bx1[dir]; }
    else         { Wsrc=d_Whh2[dir]; bx=d_bx2[dir]; }

    #pragma unroll
    for (int it=0; it<16; it++){
        int lin = tid + it*256; int r = lin>>5, seg = lin&31;
        *(uint4*)(sW + r*LDW + seg*8) = *(const uint4*)(Wsrc + (gr0+r)*256 + seg*8);
    }
    if (tid < 128) sBias[tid] = bx[gr0 + tid];
    if (LAYER==1) sWix[tid] = d_wix[dir][gr0*2 + tid];
    __syncthreads();

    const int wm = (wid&3)*32, wn = (wid>>2)*64;
    const int row = tid>>1, half = tid&1;
    const int bE = btile*128 + row;

    float creg[16];
    #pragma unroll
    for (int i=0;i<16;i++) creg[i]=0.f;

    for (int t=0; t<TT; t++){
        const int tin = dir ? (TT-1-t) : t;
        const __half* hHin = (t&1) ? h1h : h0h;
        const __half* hLin = (t&1) ? h1l : h0l;
        __half* hHout = (t&1) ? h0h : h1h;
        __half* hLout = (t&1) ? h0l : h1l;

        wmma::fragment<wmma::accumulator,16,16,16,float> acc[2][4];
        #pragma unroll
        for (int i=0;i<2;i++)
            #pragma unroll
            for (int j=0;j<4;j++) wmma::fill_fragment(acc[i][j], 0.f);

        if (t > 0){
            // ---- issue all 4 chunks via cp.async, one commit-group each ----
            #pragma unroll
            for (int kc=0; kc<4; kc++){
                #pragma unroll
                for (int it=0; it<4; it++){
                    int slot = tid + it*256;          // 1024 slots
                    int r = slot>>3, cg = slot&7;
                    size_t goff = (size_t)(btile*128 + r)*HH + kc*64 + cg*8;
                    uint32_t daddr = saddrA + kc*CHUNK_TOT + r*(LDAC*2) + cg*16;
                    CP16(daddr,          hHin + goff);
                    CP16(daddr + CHUNKB, hLin + goff);
                }
                CP_COMMIT();
            }
            // ---- MMA loop, chunk-pipelined ----
            #pragma unroll
            for (int kc=0; kc<4; kc++){
                if (kc==0) CP_WAIT(3);
                else if (kc==1) CP_WAIT(2);
                else if (kc==2) CP_WAIT(1);
                else CP_WAIT(0);
                __syncthreads();
                const __half* ah = (const __half*)(sm + OFF_A + kc*CHUNK_TOT);
                const __half* al = ah + 128*LDAC;
                #pragma unroll
                for (int k16=0; k16<4; k16++){
                    wmma::fragment<wmma::matrix_a,16,16,16,__half,wmma::row_major> fah[2], fal[2];
                    #pragma unroll
                    for (int i=0;i<2;i++){
                        wmma::load_matrix_sync(fah[i], ah + (wm+16*i)*LDAC + k16*16, LDAC);
                        wmma::load_matrix_sync(fal[i], al + (wm+16*i)*LDAC + k16*16, LDAC);
                    }
                    #pragma unroll
                    for (int j=0;j<4;j++){
                        wmma::fragment<wmma::matrix_b,16,16,16,__half,wmma::col_major> fb;
                        wmma::load_matrix_sync(fb, sW + (wn+16*j)*LDW + kc*64 + k16*16, LDW);
                        #pragma unroll
                        for (int i=0;i<2;i++){
                            wmma::mma_sync(acc[i][j], fah[i], fb, acc[i][j]);
                            wmma::mma_sync(acc[i][j], fal[i], fb, acc[i][j]);
                        }
                    }
                }
            }
        }

        // ---- Z2 prefetch (L2) before syncs ----
        __half2 zv[32];
        if (LAYER==2){
            const __half2* zp = (const __half2*)(d_Z2 + ((size_t)tin*BB + bE)*2048
                                                 + dir*1024 + gr0 + half*64);
            #pragma unroll
            for (int j=0;j<32;j++) zv[j] = zp[j];
        }

        __syncthreads();     // all MMA reads of chunk bufs done before C aliases
        #pragma unroll
        for (int i=0;i<2;i++)
            #pragma unroll
            for (int j=0;j<4;j++)
                wmma::store_matrix_sync(sC + (wm+16*i)*LDC + wn + 16*j, acc[i][j],
                                        LDC, wmma::mem_row_major);
        __syncthreads();

        // ---- LSTM cell epilogue ----
        float xv = 0.f, mb = 0.f;
        if (LAYER==1){ mb = d_m[bE]; xv = x0[bE*TT + tin] - mb; }
        const float* cr = sC + row*LDC + half*64;
        const float* mr = mrec + (size_t)bE*HH + ntile*32 + half*16;
        #pragma unroll
        for (int hh=0; hh<16; hh++){
            int rl = half*64 + hh*4;
            float g0 = cr[hh*4+0] + sBias[rl+0];
            float g1 = cr[hh*4+1] + sBias[rl+1];
            float g2 = cr[hh*4+2] + sBias[rl+2];
            float g3 = cr[hh*4+3] + sBias[rl+3];
            if (LAYER==1){
                g0 += sWix[(rl+0)*2]*xv + sWix[(rl+0)*2+1]*mb;
                g1 += sWix[(rl+1)*2]*xv + sWix[(rl+1)*2+1]*mb;
                g2 += sWix[(rl+2)*2]*xv + sWix[(rl+2)*2+1]*mb;
                g3 += sWix[(rl+3)*2]*xv + sWix[(rl+3)*2+1]*mb;
            } else {
                g0 += __low2float(zv[hh*2]);   g1 += __high2float(zv[hh*2]);
                g2 += __low2float(zv[hh*2+1]); g3 += __high2float(zv[hh*2+1]);
            }
            float ig = sigf(g0), fg = sigf(g1), gt = tanhf(g2), og = sigf(g3);
            float cn = fg*creg[hh] + ig*gt;
            float hn = og*tanhf(cn);
            creg[hh] = cn;
            int hglob = ntile*32 + half*16 + hh;
            float hm = hn * mr[hh];
            __half hhi = __float2half_rn(hm);
            hHout[(size_t)bE*HH + hglob] = hhi;
            hLout[(size_t)bE*HH + hglob] = __float2half_rn(hm - __half2float(hhi));
            if (LAYER==1){
                d_A2[((size_t)t*BB + bE)*512 + dir*HH + hglob] =
                    __float2half_rn(hn * mask2[(size_t)bE*H2 + dir*HH + hglob]);
            } else {
                d_p2[t][bE][dir*HH + hglob] = hn;
            }
        }

        // ---- group barrier (8 ntile CTAs per (btile,dir)) ----
        if (t < TT-1){
            __threadfence();
            __syncthreads();
            if (tid == 0){
                atomicAdd(ctr, 1);
                int target = 8*(t+1);
                while (__ldcg((const int*)ctr) < target) __nanosleep(20);
            }
            __syncthreads();
        }
    }
}

// ---------------- big GEMM: Z2 = A2 @ Wih2^T (2-pass) ----------------
#define SETSZ (3*128*LDG2)
#define GEMM_SMEM (2*SETSZ*2)    // 73728

__global__ void __launch_bounds__(256,2) gemm_z2(){
    extern __shared__ char sm[];
    __half* buf = (__half*)sm;
    float* sC = (float*)sm;
    const int tid = threadIdx.x, wid = tid>>5;
    const int n0 = blockIdx.x*128;
    const int m0 = blockIdx.y*128;
    const int wm = (wid&3)*32, wn = (wid>>2)*64;

    wmma::fragment<wmma::accumulator,16,16,16,float> acc[2][4];
    #pragma unroll
    for (int i=0;i<2;i++)
        #pragma unroll
        for (int j=0;j<4;j++) wmma::fill_fragment(acc[i][j], 0.f);

    #pragma unroll
    for (int it=0; it<2; it++){
        int lin = tid + it*256; int r = lin>>2, seg = lin&3;
        *(uint4*)(buf + r*LDG2 + seg*8)             = *(const uint4*)(d_A2 + (size_t)(m0+r)*512 + seg*8);
        *(uint4*)(buf + 128*LDG2 + r*LDG2 + seg*8)  = *(const uint4*)(d_Wih2hi + (size_t)(n0+r)*512 + seg*8);
        *(uint4*)(buf + 2*128*LDG2 + r*LDG2 + seg*8)= *(const uint4*)(d_Wih2lo + (size_t)(n0+r)*512 + seg*8);
    }
    __syncthreads();

    for (int kc=0; kc<16; kc++){
        uint4 v[6];
        if (kc < 15){
            #pragma unroll
            for (int it=0; it<2; it++){
                int lin = tid + it*256; int r = lin>>2, seg = lin&3;
                size_t ka = (size_t)(m0+r)*512 + (kc+1)*32 + seg*8;
                size_t kw = (size_t)(n0+r)*512 + (kc+1)*32 + seg*8;
                v[it*3+0] = *(const uint4*)(d_A2 + ka);
                v[it*3+1] = *(const uint4*)(d_Wih2hi + kw);
                v[it*3+2] = *(const uint4*)(d_Wih2lo + kw);
            }
        }
        {
            const __half* p = buf + (kc&1)*SETSZ;
            #pragma unroll
            for (int k16=0; k16<2; k16++){
                wmma::fragment<wmma::matrix_a,16,16,16,__half,wmma::row_major> fa[2];
                #pragma unroll
                for (int i=0;i<2;i++)
                    wmma::load_matrix_sync(fa[i], p + (wm+16*i)*LDG2 + k16*16, LDG2);
                #pragma unroll
                for (int j=0;j<4;j++){
                    wmma::fragment<wmma::matrix_b,16,16,16,__half,wmma::col_major> fbh, fbl;
                    wmma::load_matrix_sync(fbh, p + 128*LDG2 + (wn+16*j)*LDG2 + k16*16, LDG2);
                    wmma::load_matrix_sync(fbl, p + 2*128*LDG2 + (wn+16*j)*LDG2 + k16*16, LDG2);
                    #pragma unroll
                    for (int i=0;i<2;i++){
                        wmma::mma_sync(acc[i][j], fa[i], fbh, acc[i][j]);
                        wmma::mma_sync(acc[i][j], fa[i], fbl, acc[i][j]);
                    }
                }
            }
        }
        if (kc < 15){
            __half* q = buf + ((kc+1)&1)*SETSZ;
            #pragma unroll
            for (int it=0; it<2; it++){
                int lin = tid + it*256; int r = lin>>2, seg = lin&3;
                *(uint4*)(q + r*LDG2 + seg*8)              = v[it*3+0];
                *(uint4*)(q + 128*LDG2 + r*LDG2 + seg*8)   = v[it*3+1];
                *(uint4*)(q + 2*128*LDG2 + r*LDG2 + seg*8) = v[it*3+2];
            }
        }
        __syncthreads();
    }

    #pragma unroll
    for (int i=0;i<2;i++)
        #pragma unroll
        for (int j=0;j<4;j++)
            wmma::store_matrix_sync(sC + (wm+16*i)*LDC + wn + 16*j, acc[i][j],
                                    LDC, wmma::mem_row_major);
    __syncthreads();
    const int row = tid>>1, half = tid&1;
    __half2* zp = (__half2*)(d_Z2 + (size_t)(m0+row)*2048 + n0 + half*64);
    const float* cr = sC + row*LDC + half*64;
    #pragma unroll
    for (int j=0;j<32;j++)
        zp[j] = __floats2half2_rn(cr[2*j], cr[2*j+1]);
}

// ---------------- output projection ----------------
__global__ void proj_kernel(const float* __restrict__ Wout,
                            const float* __restrict__ bout,
                            const float* __restrict__ mask4,
                            float* __restrict__ out)
{
    int w = blockIdx.x*(blockDim.x>>5) + (threadIdx.x>>5);
    int lane = threadIdx.x & 31;
    if (w >= BB*TT) return;
    int b = w/TT, t = w%TT;
    float s = 0.f;
    #pragma unroll
    for (int j = lane; j < H2; j += 32)
        s += d_p2[t][b][j] * mask4[b*H2 + j] * Wout[j];
    #pragma unroll
    for (int o = 16; o > 0; o >>= 1) s += __shfl_xor_sync(0xffffffffu, s, o);
    if (lane == 0) out[b*TT + t] = s + bout[0] + d_m[b];
}

// ---------------- launcher ----------------
extern "C" void kernel_launch(void* const* d_in, const int* in_sizes, int n_in,
                              void* d_out, int out_size)
{
    const float* x0    = (const float*)d_in[0];
    const float* Wih1f = (const float*)d_in[1];
    const float* Whh1f = (const float*)d_in[2];
    const float* bih1f = (const float*)d_in[3];
    const float* bhh1f = (const float*)d_in[4];
    const float* Wih1b = (const float*)d_in[5];
    const float* Whh1b = (const float*)d_in[6];
    const float* bih1b = (const float*)d_in[7];
    const float* bhh1b = (const float*)d_in[8];
    const float* Wih2f = (const float*)d_in[9];
    const float* Whh2f = (const float*)d_in[10];
    const float* bih2f = (const float*)d_in[11];
    const float* bhh2f = (const float*)d_in[12];
    const float* Wih2b = (const float*)d_in[13];
    const float* Whh2b = (const float*)d_in[14];
    const float* bih2b = (const float*)d_in[15];
    const float* bhh2b = (const float*)d_in[16];
    const float* Wout  = (const float*)d_in[17];
    const float* bout  = (const float*)d_in[18];
    const float* mask1 = (const float*)d_in[19];
    const float* mask2 = (const float*)d_in[20];
    const float* mask3 = (const float*)d_in[21];
    const float* mask4 = (const float*)d_in[22];
    float* out = (float*)d_out;

    cudaFuncSetAttribute(lstm_persist<1>, cudaFuncAttributeMaxDynamicSharedMemorySize, PERSIST_SMEM);
    cudaFuncSetAttribute(lstm_persist<2>, cudaFuncAttributeMaxDynamicSharedMemorySize, PERSIST_SMEM);
    cudaFuncSetAttribute(gemm_z2, cudaFuncAttributeMaxDynamicSharedMemorySize, GEMM_SMEM);

    mean_kernel<<<(BB+255)/256, 256>>>(x0);
    zero_kernel<<<1, 32>>>();
    prep_weights<<<1024, 256>>>(Whh1f, Whh1b, Wih2f, Whh2f, Wih2b, Whh2b,
                                Wih1f, Wih1b,
                                bih1f, bhh1f, bih1b, bhh1b,
                                bih2f, bhh2f, bih2b, bhh2b);

    lstm_persist<1><<<dim3(8,8,2), 256, PERSIST_SMEM>>>(x0, mask1, mask2);
    gemm_z2<<<dim3(16,800), 256, GEMM_SMEM>>>();
    lstm_persist<2><<<dim3(8,8,2), 256, PERSIST_SMEM>>>(nullptr, mask3, nullptr);

    proj_kernel<<<(BB*TT+7)/8, 256>>>(Wout, bout, mask4, out);
}

// round 11
// speedup vs baseline: 2.4250x; 1.4872x over previous
#include <cuda_runtime.h>
#include <cuda_fp16.h>
#include <mma.h>
#include <cstdint>
#include <math.h>

using namespace nvcuda;

#define BB 1024
#define TT 100
#define HH 256
#define H2 512
#define LDW 264          // resident W smem lead dim (fp16 elems)
#define LDAC 72          // A chunk smem lead dim (fp16 elems)
#define LDC 132          // epilogue C lead dim (f32)
#define LDG2 48          // big-GEMM chunk lead dim

// ---------------- device scratch ----------------
__device__ float d_m[BB];
__device__ __half d_hp[2][2][2][BB*HH];   // [layer][ping][dir] masked h, fp16
__device__ float d_p2[TT][BB][H2];
__device__ __half d_W1[2][1024*256];      // layer1 Whh fp16, r'=4h+g
__device__ __half d_Whh2[2][1024*256];
__device__ __half d_Wih2[2048*512];
__device__ float d_bx1[2][1024];
__device__ float d_bx2[2][1024];
__device__ float d_wix[2][1024*2];
__device__ __half d_A2[(size_t)TT*BB*512];
__device__ __half d_Z2[(size_t)TT*BB*2048];
__device__ int d_bar[2][16];

__device__ __forceinline__ float tanh_fast(float x){
    float y; asm("tanh.approx.f32 %0, %1;" : "=f"(y) : "f"(x)); return y;
}
__device__ __forceinline__ float sig_fast(float x){
    return 0.5f + 0.5f*tanh_fast(0.5f*x);
}

#define CP16(s,g) asm volatile("cp.async.cg.shared.global [%0], [%1], 16;"::"r"(s),"l"(g):"memory")
#define CP_COMMIT() asm volatile("cp.async.commit_group;":::"memory")
#define CP_WAIT(n) asm volatile("cp.async.wait_group %0;"::"n"(n):"memory")

__device__ __forceinline__ uint32_t smem_u32(const void* p){
    uint32_t a;
    asm("{ .reg .u64 t; cvta.to.shared.u64 t, %1; cvt.u32.u64 %0, t; }":"=r"(a):"l"(p));
    return a;
}

// ---------------- mean ----------------
__global__ void mean_kernel(const float* __restrict__ x0){
    int b = blockIdx.x*blockDim.x + threadIdx.x;
    if (b < BB){
        float s = 0.f;
        #pragma unroll 4
        for (int t=0; t<TT; t++) s += x0[b*TT+t];
        d_m[b] = s*(1.0f/TT);
    }
}

// ---------------- zero barriers ----------------
__global__ void zero_kernel(){
    int i = blockIdx.x*blockDim.x + threadIdx.x;
    if (i < 16){ d_bar[0][i]=0; d_bar[1][i]=0; }
}

// ---------------- weight prep ----------------
__global__ void prep_weights(
    const float* __restrict__ Whh1f, const float* __restrict__ Whh1b,
    const float* __restrict__ Wih2f, const float* __restrict__ Whh2f,
    const float* __restrict__ Wih2b, const float* __restrict__ Whh2b,
    const float* __restrict__ Wih1f, const float* __restrict__ Wih1b,
    const float* __restrict__ bih1f, const float* __restrict__ bhh1f,
    const float* __restrict__ bih1b, const float* __restrict__ bhh1b,
    const float* __restrict__ bih2f, const float* __restrict__ bhh2f,
    const float* __restrict__ bih2b, const float* __restrict__ bhh2b)
{
    int stride = gridDim.x*blockDim.x;
    int idx = blockIdx.x*blockDim.x + threadIdx.x;
    for (int i = idx; i < 2*1024*256; i += stride){
        int dir = i/(1024*256); int r = (i/256)%1024; int k = i%256;
        int h = r>>2, g = r&3;
        const float* W1 = dir ? Whh1b : Whh1f;
        const float* W2 = dir ? Whh2b : Whh2f;
        d_W1[dir][r*256+k]   = __float2half_rn(W1[(g*256+h)*256 + k]);
        d_Whh2[dir][r*256+k] = __float2half_rn(W2[(g*256+h)*256 + k]);
    }
    for (int i = idx; i < 2048*512; i += stride){
        int n = i>>9, k = i&511;
        int dir = n>>10, r = n&1023;
        int h = r>>2, g = r&3;
        const float* W = dir ? Wih2b : Wih2f;
        d_Wih2[i] = __float2half_rn(W[(g*256+h)*512 + k]);
    }
    for (int i = idx; i < 2*1024; i += stride){
        int dir = i>>10; int r = i&1023;
        int h = r>>2, g = r&3;
        const float* b1i = dir ? bih1b : bih1f; const float* b1h = dir ? bhh1b : bhh1f;
        const float* b2i = dir ? bih2b : bih2f; const float* b2h = dir ? bhh2b : bhh2f;
        d_bx1[dir][r] = b1i[g*256+h] + b1h[g*256+h];
        d_bx2[dir][r] = b2i[g*256+h] + b2h[g*256+h];
        const float* Wi = dir ? Wih1b : Wih1f;
        d_wix[dir][r*2+0] = Wi[(g*256+h)*2 + 0];
        d_wix[dir][r*2+1] = Wi[(g*256+h)*2 + 1];
    }
}

// ---------------- persistent recurrent LSTM ----------------
// grid (8 ntile, 8 btile, 2 dir) = 128 CTAs. W fp16 resident.
// h stored pre-masked fp16 -> staging is pure cp.async copy, 4 chunk-groups
// pipelined against the single-pass fp16 MMA loop. c in registers.
#define WBYTES (128*LDW*2)          // 67584
#define CHUNKB (128*LDAC*2)         // 18432
#define OFF_A (2048 + WBYTES)       // 69632
#define PERSIST_SMEM (OFF_A + 4*CHUNKB)   // 143360

template<int LAYER>
__global__ void __launch_bounds__(256,1) lstm_persist(
    const float* __restrict__ x0,
    const float* __restrict__ mrec,     // mask1 (L1) / mask3 (L2)
    const float* __restrict__ mask2)    // L1 only
{
    extern __shared__ char sm[];
    float* sBias = (float*)sm;
    float* sWix  = (float*)(sm + 512);
    __half* sW  = (__half*)(sm + 2048);
    float* sC = (float*)(sm + OFF_A);
    const uint32_t saddrA = smem_u32(sm) + OFF_A;

    const int tid = threadIdx.x, wid = tid>>5;
    const int ntile = blockIdx.x, btile = blockIdx.y, dir = blockIdx.z;
    const int gr0 = ntile*128;
    int* ctr = &d_bar[LAYER-1][dir*8 + btile];

    const __half* Wsrc; const float* bx;
    __half *h0 = d_hp[LAYER-1][0][dir], *h1 = d_hp[LAYER-1][1][dir];
    if (LAYER==1){ Wsrc=d_W1[dir];   bx=d_bx1[dir]; }
    else         { Wsrc=d_Whh2[dir]; bx=d_bx2[dir]; }

    #pragma unroll
    for (int it=0; it<16; it++){
        int lin = tid + it*256; int r = lin>>5, seg = lin&31;
        *(uint4*)(sW + r*LDW + seg*8) = *(const uint4*)(Wsrc + (gr0+r)*256 + seg*8);
    }
    if (tid < 128) sBias[tid] = bx[gr0 + tid];
    if (LAYER==1) sWix[tid] = d_wix[dir][gr0*2 + tid];
    __syncthreads();

    const int wm = (wid&3)*32, wn = (wid>>2)*64;
    const int row = tid>>1, half = tid&1;
    const int bE = btile*128 + row;

    float creg[16];
    #pragma unroll
    for (int i=0;i<16;i++) creg[i]=0.f;

    for (int t=0; t<TT; t++){
        const int tin = dir ? (TT-1-t) : t;
        const __half* hIn = (t&1) ? h1 : h0;
        __half* hOut = (t&1) ? h0 : h1;

        wmma::fragment<wmma::accumulator,16,16,16,float> acc[2][4];
        #pragma unroll
        for (int i=0;i<2;i++)
            #pragma unroll
            for (int j=0;j<4;j++) wmma::fill_fragment(acc[i][j], 0.f);

        if (t > 0){
            // ---- issue all 4 chunks via cp.async, one commit-group each ----
            #pragma unroll
            for (int kc=0; kc<4; kc++){
                #pragma unroll
                for (int it=0; it<4; it++){
                    int slot = tid + it*256;          // 1024 slots
                    int r = slot>>3, cg = slot&7;
                    size_t goff = (size_t)(btile*128 + r)*HH + kc*64 + cg*8;
                    uint32_t daddr = saddrA + kc*CHUNKB + r*(LDAC*2) + cg*16;
                    CP16(daddr, hIn + goff);
                }
                CP_COMMIT();
            }
            // ---- MMA loop, chunk-pipelined, single pass ----
            #pragma unroll
            for (int kc=0; kc<4; kc++){
                if (kc==0) CP_WAIT(3);
                else if (kc==1) CP_WAIT(2);
                else if (kc==2) CP_WAIT(1);
                else CP_WAIT(0);
                __syncthreads();
                const __half* ah = (const __half*)(sm + OFF_A + kc*CHUNKB);
                #pragma unroll
                for (int k16=0; k16<4; k16++){
                    wmma::fragment<wmma::matrix_a,16,16,16,__half,wmma::row_major> fah[2];
                    #pragma unroll
                    for (int i=0;i<2;i++)
                        wmma::load_matrix_sync(fah[i], ah + (wm+16*i)*LDAC + k16*16, LDAC);
                    #pragma unroll
                    for (int j=0;j<4;j++){
                        wmma::fragment<wmma::matrix_b,16,16,16,__half,wmma::col_major> fb;
                        wmma::load_matrix_sync(fb, sW + (wn+16*j)*LDW + kc*64 + k16*16, LDW);
                        #pragma unroll
                        for (int i=0;i<2;i++)
                            wmma::mma_sync(acc[i][j], fah[i], fb, acc[i][j]);
                    }
                }
            }
        }

        // ---- Z2 prefetch (L2) before syncs ----
        __half2 zv[32];
        if (LAYER==2){
            const __half2* zp = (const __half2*)(d_Z2 + ((size_t)tin*BB + bE)*2048
                                                 + dir*1024 + gr0 + half*64);
            #pragma unroll
            for (int j=0;j<32;j++) zv[j] = zp[j];
        }

        __syncthreads();     // all MMA reads of chunk bufs done before C aliases
        #pragma unroll
        for (int i=0;i<2;i++)
            #pragma unroll
            for (int j=0;j<4;j++)
                wmma::store_matrix_sync(sC + (wm+16*i)*LDC + wn + 16*j, acc[i][j],
                                        LDC, wmma::mem_row_major);
        __syncthreads();

        // ---- LSTM cell epilogue ----
        float xv = 0.f, mb = 0.f;
        if (LAYER==1){ mb = d_m[bE]; xv = x0[bE*TT + tin] - mb; }
        const float* cr = sC + row*LDC + half*64;
        const float* mr = mrec + (size_t)bE*HH + ntile*32 + half*16;
        #pragma unroll
        for (int hh=0; hh<16; hh++){
            int rl = half*64 + hh*4;
            float g0 = cr[hh*4+0] + sBias[rl+0];
            float g1 = cr[hh*4+1] + sBias[rl+1];
            float g2 = cr[hh*4+2] + sBias[rl+2];
            float g3 = cr[hh*4+3] + sBias[rl+3];
            if (LAYER==1){
                g0 += sWix[(rl+0)*2]*xv + sWix[(rl+0)*2+1]*mb;
                g1 += sWix[(rl+1)*2]*xv + sWix[(rl+1)*2+1]*mb;
                g2 += sWix[(rl+2)*2]*xv + sWix[(rl+2)*2+1]*mb;
                g3 += sWix[(rl+3)*2]*xv + sWix[(rl+3)*2+1]*mb;
            } else {
                g0 += __low2float(zv[hh*2]);   g1 += __high2float(zv[hh*2]);
                g2 += __low2float(zv[hh*2+1]); g3 += __high2float(zv[hh*2+1]);
            }
            float ig = sig_fast(g0), fg = sig_fast(g1), og = sig_fast(g3);
            float gt = tanh_fast(g2);
            float cn = fg*creg[hh] + ig*gt;
            float hn = og*tanh_fast(cn);
            creg[hh] = cn;
            int hglob = ntile*32 + half*16 + hh;
            hOut[(size_t)bE*HH + hglob] = __float2half_rn(hn * mr[hh]);
            if (LAYER==1){
                d_A2[((size_t)t*BB + bE)*512 + dir*HH + hglob] =
                    __float2half_rn(hn * mask2[(size_t)bE*H2 + dir*HH + hglob]);
            } else {
                d_p2[t][bE][dir*HH + hglob] = hn;
            }
        }

        // ---- group barrier (8 ntile CTAs per (btile,dir)) ----
        if (t < TT-1){
            __threadfence();
            __syncthreads();
            if (tid == 0){
                atomicAdd(ctr, 1);
                int target = 8*(t+1);
                while (__ldcg((const int*)ctr) < target) __nanosleep(20);
            }
            __syncthreads();
        }
    }
}

// ---------------- big GEMM: Z2 = A2 @ Wih2^T (single-pass fp16) ----------------
#define SETSZ (2*128*LDG2)
#define CBYTES (128*LDC*4)              // 67584 — fp32 C tile in epilogue
#define GEMM_SMEM CBYTES                // staging (49152 B) fits inside this

__global__ void __launch_bounds__(256,2) gemm_z2(){
    extern __shared__ char sm[];
    __half* buf = (__half*)sm;
    float* sC = (float*)sm;
    const int tid = threadIdx.x, wid = tid>>5;
    const int n0 = blockIdx.x*128;
    const int m0 = blockIdx.y*128;
    const int wm = (wid&3)*32, wn = (wid>>2)*64;

    wmma::fragment<wmma::accumulator,16,16,16,float> acc[2][4];
    #pragma unroll
    for (int i=0;i<2;i++)
        #pragma unroll
        for (int j=0;j<4;j++) wmma::fill_fragment(acc[i][j], 0.f);

    #pragma unroll
    for (int it=0; it<2; it++){
        int lin = tid + it*256; int r = lin>>2, seg = lin&3;
        *(uint4*)(buf + r*LDG2 + seg*8)            = *(const uint4*)(d_A2 + (size_t)(m0+r)*512 + seg*8);
        *(uint4*)(buf + 128*LDG2 + r*LDG2 + seg*8) = *(const uint4*)(d_Wih2 + (size_t)(n0+r)*512 + seg*8);
    }
    __syncthreads();

    for (int kc=0; kc<16; kc++){
        uint4 v[4];
        if (kc < 15){
            #pragma unroll
            for (int it=0; it<2; it++){
                int lin = tid + it*256; int r = lin>>2, seg = lin&3;
                size_t ka = (size_t)(m0+r)*512 + (kc+1)*32 + seg*8;
                size_t kw = (size_t)(n0+r)*512 + (kc+1)*32 + seg*8;
                v[it*2+0] = *(const uint4*)(d_A2 + ka);
                v[it*2+1] = *(const uint4*)(d_Wih2 + kw);
            }
        }
        {
            const __half* p = buf + (kc&1)*SETSZ;
            #pragma unroll
            for (int k16=0; k16<2; k16++){
                wmma::fragment<wmma::matrix_a,16,16,16,__half,wmma::row_major> fa[2];
                #pragma unroll
                for (int i=0;i<2;i++)
                    wmma::load_matrix_sync(fa[i], p + (wm+16*i)*LDG2 + k16*16, LDG2);
                #pragma unroll
                for (int j=0;j<4;j++){
                    wmma::fragment<wmma::matrix_b,16,16,16,__half,wmma::col_major> fb;
                    wmma::load_matrix_sync(fb, p + 128*LDG2 + (wn+16*j)*LDG2 + k16*16, LDG2);
                    #pragma unroll
                    for (int i=0;i<2;i++)
                        wmma::mma_sync(acc[i][j], fa[i], fb, acc[i][j]);
                }
            }
        }
        if (kc < 15){
            __half* q = buf + ((kc+1)&1)*SETSZ;
            #pragma unroll
            for (int it=0; it<2; it++){
                int lin = tid + it*256; int r = lin>>2, seg = lin&3;
                *(uint4*)(q + r*LDG2 + seg*8)            = v[it*2+0];
                *(uint4*)(q + 128*LDG2 + r*LDG2 + seg*8) = v[it*2+1];
            }
        }
        __syncthreads();
    }

    #pragma unroll
    for (int i=0;i<2;i++)
        #pragma unroll
        for (int j=0;j<4;j++)
            wmma::store_matrix_sync(sC + (wm+16*i)*LDC + wn + 16*j, acc[i][j],
                                    LDC, wmma::mem_row_major);
    __syncthreads();
    const int row = tid>>1, half = tid&1;
    __half2* zp = (__half2*)(d_Z2 + (size_t)(m0+row)*2048 + n0 + half*64);
    const float* cr = sC + row*LDC + half*64;
    #pragma unroll
    for (int j=0;j<32;j++)
        zp[j] = __floats2half2_rn(cr[2*j], cr[2*j+1]);
}

// ---------------- output projection ----------------
__global__ void proj_kernel(const float* __restrict__ Wout,
                            const float* __restrict__ bout,
                            const float* __restrict__ mask4,
                            float* __restrict__ out)
{
    int w = blockIdx.x*(blockDim.x>>5) + (threadIdx.x>>5);
    int lane = threadIdx.x & 31;
    if (w >= BB*TT) return;
    int b = w/TT, t = w%TT;
    float s = 0.f;
    #pragma unroll
    for (int j = lane; j < H2; j += 32)
        s += d_p2[t][b][j] * mask4[b*H2 + j] * Wout[j];
    #pragma unroll
    for (int o = 16; o > 0; o >>= 1) s += __shfl_xor_sync(0xffffffffu, s, o);
    if (lane == 0) out[b*TT + t] = s + bout[0] + d_m[b];
}

// ---------------- launcher ----------------
extern "C" void kernel_launch(void* const* d_in, const int* in_sizes, int n_in,
                              void* d_out, int out_size)
{
    const float* x0    = (const float*)d_in[0];
    const float* Wih1f = (const float*)d_in[1];
    const float* Whh1f = (const float*)d_in[2];
    const float* bih1f = (const float*)d_in[3];
    const float* bhh1f = (const float*)d_in[4];
    const float* Wih1b = (const float*)d_in[5];
    const float* Whh1b = (const float*)d_in[6];
    const float* bih1b = (const float*)d_in[7];
    const float* bhh1b = (const float*)d_in[8];
    const float* Wih2f = (const float*)d_in[9];
    const float* Whh2f = (const float*)d_in[10];
    const float* bih2f = (const float*)d_in[11];
    const float* bhh2f = (const float*)d_in[12];
    const float* Wih2b = (const float*)d_in[13];
    const float* Whh2b = (const float*)d_in[14];
    const float* bih2b = (const float*)d_in[15];
    const float* bhh2b = (const float*)d_in[16];
    const float* Wout  = (const float*)d_in[17];
    const float* bout  = (const float*)d_in[18];
    const float* mask1 = (const float*)d_in[19];
    const float* mask2 = (const float*)d_in[20];
    const float* mask3 = (const float*)d_in[21];
    const float* mask4 = (const float*)d_in[22];
    float* out = (float*)d_out;

    cudaFuncSetAttribute(lstm_persist<1>, cudaFuncAttributeMaxDynamicSharedMemorySize, PERSIST_SMEM);
    cudaFuncSetAttribute(lstm_persist<2>, cudaFuncAttributeMaxDynamicSharedMemorySize, PERSIST_SMEM);
    cudaFuncSetAttribute(gemm_z2, cudaFuncAttributeMaxDynamicSharedMemorySize, GEMM_SMEM);

    mean_kernel<<<(BB+255)/256, 256>>>(x0);
    zero_kernel<<<1, 32>>>();
    prep_weights<<<1024, 256>>>(Whh1f, Whh1b, Wih2f, Whh2f, Wih2b, Whh2b,
                                Wih1f, Wih1b,
                                bih1f, bhh1f, bih1b, bhh1b,
                                bih2f, bhh2f, bih2b, bhh2b);

    lstm_persist<1><<<dim3(8,8,2), 256, PERSIST_SMEM>>>(x0, mask1, mask2);
    gemm_z2<<<dim3(16,800), 256, GEMM_SMEM>>>();
    lstm_persist<2><<<dim3(8,8,2), 256, PERSIST_SMEM>>>(nullptr, mask3, nullptr);

    proj_kernel<<<(BB*TT+7)/8, 256>>>(Wout, bout, mask4, out);
}

// round 15
// speedup vs baseline: 2.6143x; 1.0781x over previous
#include <cuda_runtime.h>
#include <cuda_fp16.h>
#include <mma.h>
#include <cstdint>
#include <math.h>

using namespace nvcuda;

#define BB 1024
#define TT 100
#define HH 256
#define H2 512
#define LDW 264          // resident W smem lead dim (fp16 elems)
#define LDAC 72          // A chunk smem lead dim (fp16 elems)
#define LDC 132          // epilogue C lead dim (f32)
#define LDG2 48          // big-GEMM chunk lead dim

// ---------------- device scratch ----------------
__device__ float d_m[BB];
__device__ __half d_hp[2][2][2][BB*HH];   // [layer][ping][dir] masked h, fp16
__device__ float d_p2[TT][BB][H2];
__device__ __half d_W1[2][1024*256];      // layer1 Whh fp16, r'=4h+g
__device__ __half d_Whh2[2][1024*256];
__device__ __half d_Wih2[2048*512];
__device__ float d_bx1[2][1024];
__device__ float d_bx2[2][1024];
__device__ float d_wix[2][1024*2];
__device__ __half d_A2[(size_t)TT*BB*512];
__device__ __half d_Z2[(size_t)TT*BB*2048];
__device__ int d_bar[2][16];

__device__ __forceinline__ float tanh_fast(float x){
    float y; asm("tanh.approx.f32 %0, %1;" : "=f"(y) : "f"(x)); return y;
}
__device__ __forceinline__ float sig_fast(float x){
    return 0.5f + 0.5f*tanh_fast(0.5f*x);
}

#define CP16(s,g) asm volatile("cp.async.cg.shared.global [%0], [%1], 16;"::"r"(s),"l"(g):"memory")
#define CP_COMMIT() asm volatile("cp.async.commit_group;":::"memory")
#define CP_WAIT(n) asm volatile("cp.async.wait_group %0;"::"n"(n):"memory")

__device__ __forceinline__ uint32_t smem_u32(const void* p){
    uint32_t a;
    asm("{ .reg .u64 t; cvta.to.shared.u64 t, %1; cvt.u32.u64 %0, t; }":"=r"(a):"l"(p));
    return a;
}

// ---------------- mean ----------------
__global__ void mean_kernel(const float* __restrict__ x0){
    int b = blockIdx.x*blockDim.x + threadIdx.x;
    if (b < BB){
        float s = 0.f;
        #pragma unroll 4
        for (int t=0; t<TT; t++) s += x0[b*TT+t];
        d_m[b] = s*(1.0f/TT);
    }
}

// ---------------- zero barriers ----------------
__global__ void zero_kernel(){
    int i = blockIdx.x*blockDim.x + threadIdx.x;
    if (i < 16){ d_bar[0][i]=0; d_bar[1][i]=0; }
}

// ---------------- weight prep ----------------
__global__ void prep_weights(
    const float* __restrict__ Whh1f, const float* __restrict__ Whh1b,
    const float* __restrict__ Wih2f, const float* __restrict__ Whh2f,
    const float* __restrict__ Wih2b, const float* __restrict__ Whh2b,
    const float* __restrict__ Wih1f, const float* __restrict__ Wih1b,
    const float* __restrict__ bih1f, const float* __restrict__ bhh1f,
    const float* __restrict__ bih1b, const float* __restrict__ bhh1b,
    const float* __restrict__ bih2f, const float* __restrict__ bhh2f,
    const float* __restrict__ bih2b, const float* __restrict__ bhh2b)
{
    int stride = gridDim.x*blockDim.x;
    int idx = blockIdx.x*blockDim.x + threadIdx.x;
    for (int i = idx; i < 2*1024*256; i += stride){
        int dir = i/(1024*256); int r = (i/256)%1024; int k = i%256;
        int h = r>>2, g = r&3;
        const float* W1 = dir ? Whh1b : Whh1f;
        const float* W2 = dir ? Whh2b : Whh2f;
        d_W1[dir][r*256+k]   = __float2half_rn(W1[(g*256+h)*256 + k]);
        d_Whh2[dir][r*256+k] = __float2half_rn(W2[(g*256+h)*256 + k]);
    }
    for (int i = idx; i < 2048*512; i += stride){
        int n = i>>9, k = i&511;
        int dir = n>>10, r = n&1023;
        int h = r>>2, g = r&3;
        const float* W = dir ? Wih2b : Wih2f;
        d_Wih2[i] = __float2half_rn(W[(g*256+h)*512 + k]);
    }
    for (int i = idx; i < 2*1024; i += stride){
        int dir = i>>10; int r = i&1023;
        int h = r>>2, g = r&3;
        const float* b1i = dir ? bih1b : bih1f; const float* b1h = dir ? bhh1b : bhh1f;
        const float* b2i = dir ? bih2b : bih2f; const float* b2h = dir ? bhh2b : bhh2f;
        d_bx1[dir][r] = b1i[g*256+h] + b1h[g*256+h];
        d_bx2[dir][r] = b2i[g*256+h] + b2h[g*256+h];
        const float* Wi = dir ? Wih1b : Wih1f;
        d_wix[dir][r*2+0] = Wi[(g*256+h)*2 + 0];
        d_wix[dir][r*2+1] = Wi[(g*256+h)*2 + 1];
    }
}

// ---------------- persistent recurrent LSTM ----------------
// grid (8 ntile, 8 btile, 2 dir) = 128 CTAs, 512 threads (16 warps).
// W fp16 resident. h pre-masked fp16 -> pure cp.async staging, 4 chunk-groups
// pipelined against the single-pass fp16 MMA loop. Warp tile 32x32 (4x4 grid).
// Dedicated C region (no aliasing). c state in registers.
#define WBYTES (128*LDW*2)          // 67584
#define CHUNKB (128*LDAC*2)         // 18432
#define OFF_A (2048 + WBYTES)       // 69632
#define OFF_C (OFF_A + 4*CHUNKB)    // 143360
#define CBYTES (128*LDC*4)          // 67584
#define PERSIST_SMEM (OFF_C + CBYTES)   // 210944

template<int LAYER>
__global__ void __launch_bounds__(512,1) lstm_persist(
    const float* __restrict__ x0,
    const float* __restrict__ mrec,     // mask1 (L1) / mask3 (L2)
    const float* __restrict__ mask2)    // L1 only
{
    extern __shared__ char sm[];
    float* sBias = (float*)sm;
    float* sWix  = (float*)(sm + 512);
    __half* sW  = (__half*)(sm + 2048);
    float* sC = (float*)(sm + OFF_C);
    const uint32_t saddrA = smem_u32(sm) + OFF_A;

    const int tid = threadIdx.x, wid = tid>>5;
    const int ntile = blockIdx.x, btile = blockIdx.y, dir = blockIdx.z;
    const int gr0 = ntile*128;
    int* ctr = &d_bar[LAYER-1][dir*8 + btile];

    const __half* Wsrc; const float* bx;
    __half *h0 = d_hp[LAYER-1][0][dir], *h1 = d_hp[LAYER-1][1][dir];
    if (LAYER==1){ Wsrc=d_W1[dir];   bx=d_bx1[dir]; }
    else         { Wsrc=d_Whh2[dir]; bx=d_bx2[dir]; }

    #pragma unroll
    for (int it=0; it<8; it++){
        int lin = tid + it*512; int r = lin>>5, seg = lin&31;
        *(uint4*)(sW + r*LDW + seg*8) = *(const uint4*)(Wsrc + (gr0+r)*256 + seg*8);
    }
    if (tid < 128) sBias[tid] = bx[gr0 + tid];
    if (LAYER==1 && tid < 256) sWix[tid] = d_wix[dir][gr0*2 + tid];
    __syncthreads();

    const int wm = (wid&3)*32, wn = (wid>>2)*32;
    const int row = tid>>2, q = tid&3;
    const int bE = btile*128 + row;

    float creg[8];
    #pragma unroll
    for (int i=0;i<8;i++) creg[i]=0.f;

    for (int t=0; t<TT; t++){
        const int tin = dir ? (TT-1-t) : t;
        const __half* hIn = (t&1) ? h1 : h0;
        __half* hOut = (t&1) ? h0 : h1;

        wmma::fragment<wmma::accumulator,16,16,16,float> acc[2][2];
        #pragma unroll
        for (int i=0;i<2;i++)
            #pragma unroll
            for (int j=0;j<2;j++) wmma::fill_fragment(acc[i][j], 0.f);

        if (t > 0){
            // ---- issue all 4 chunks via cp.async, one commit-group each ----
            #pragma unroll
            for (int kc=0; kc<4; kc++){
                #pragma unroll
                for (int it=0; it<2; it++){
                    int slot = tid + it*512;          // 1024 slots
                    int r = slot>>3, cg = slot&7;
                    size_t goff = (size_t)(btile*128 + r)*HH + kc*64 + cg*8;
                    uint32_t daddr = saddrA + kc*CHUNKB + r*(LDAC*2) + cg*16;
                    CP16(daddr, hIn + goff);
                }
                CP_COMMIT();
            }
            // ---- MMA loop, chunk-pipelined, single pass ----
            #pragma unroll
            for (int kc=0; kc<4; kc++){
                if (kc==0) CP_WAIT(3);
                else if (kc==1) CP_WAIT(2);
                else if (kc==2) CP_WAIT(1);
                else CP_WAIT(0);
                __syncthreads();
                const __half* ah = (const __half*)(sm + OFF_A + kc*CHUNKB);
                #pragma unroll
                for (int k16=0; k16<4; k16++){
                    wmma::fragment<wmma::matrix_a,16,16,16,__half,wmma::row_major> fa[2];
                    wmma::fragment<wmma::matrix_b,16,16,16,__half,wmma::col_major> fb[2];
                    #pragma unroll
                    for (int i=0;i<2;i++)
                        wmma::load_matrix_sync(fa[i], ah + (wm+16*i)*LDAC + k16*16, LDAC);
                    #pragma unroll
                    for (int j=0;j<2;j++)
                        wmma::load_matrix_sync(fb[j], sW + (wn+16*j)*LDW + kc*64 + k16*16, LDW);
                    #pragma unroll
                    for (int i=0;i<2;i++)
                        #pragma unroll
                        for (int j=0;j<2;j++)
                            wmma::mma_sync(acc[i][j], fa[i], fb[j], acc[i][j]);
                }
            }
        }

        // ---- Z2 prefetch (L2) early ----
        __half2 zv[16];
        if (LAYER==2){
            const __half2* zp = (const __half2*)(d_Z2 + ((size_t)tin*BB + bE)*2048
                                                 + dir*1024 + gr0 + q*32);
            #pragma unroll
            for (int j=0;j<16;j++) zv[j] = zp[j];
        }

        // ---- dump C (dedicated region; per-warp disjoint) ----
        #pragma unroll
        for (int i=0;i<2;i++)
            #pragma unroll
            for (int j=0;j<2;j++)
                wmma::store_matrix_sync(sC + (wm+16*i)*LDC + wn + 16*j, acc[i][j],
                                        LDC, wmma::mem_row_major);
        __syncthreads();

        // ---- LSTM cell epilogue: each thread 8 cells ----
        float xv = 0.f, mb = 0.f;
        if (LAYER==1){ mb = d_m[bE]; xv = x0[bE*TT + tin] - mb; }
        const float* cr = sC + row*LDC + q*32;
        const float* mr = mrec + (size_t)bE*HH + ntile*32 + q*8;
        #pragma unroll
        for (int hh=0; hh<8; hh++){
            int rl = q*32 + hh*4;
            float g0 = cr[hh*4+0] + sBias[rl+0];
            float g1 = cr[hh*4+1] + sBias[rl+1];
            float g2 = cr[hh*4+2] + sBias[rl+2];
            float g3 = cr[hh*4+3] + sBias[rl+3];
            if (LAYER==1){
                g0 += sWix[(rl+0)*2]*xv + sWix[(rl+0)*2+1]*mb;
                g1 += sWix[(rl+1)*2]*xv + sWix[(rl+1)*2+1]*mb;
                g2 += sWix[(rl+2)*2]*xv + sWix[(rl+2)*2+1]*mb;
                g3 += sWix[(rl+3)*2]*xv + sWix[(rl+3)*2+1]*mb;
            } else {
                g0 += __low2float(zv[hh*2]);   g1 += __high2float(zv[hh*2]);
                g2 += __low2float(zv[hh*2+1]); g3 += __high2float(zv[hh*2+1]);
            }
            float ig = sig_fast(g0), fg = sig_fast(g1), og = sig_fast(g3);
            float gt = tanh_fast(g2);
            float cn = fg*creg[hh] + ig*gt;
            float hn = og*tanh_fast(cn);
            creg[hh] = cn;
            int hglob = ntile*32 + q*8 + hh;
            hOut[(size_t)bE*HH + hglob] = __float2half_rn(hn * mr[hh]);
            if (LAYER==1){
                d_A2[((size_t)t*BB + bE)*512 + dir*HH + hglob] =
                    __float2half_rn(hn * mask2[(size_t)bE*H2 + dir*HH + hglob]);
            } else {
                d_p2[t][bE][dir*HH + hglob] = hn;
            }
        }

        // ---- group barrier (8 ntile CTAs per (btile,dir)) ----
        if (t < TT-1){
            __threadfence();
            __syncthreads();
            if (tid == 0){
                atomicAdd(ctr, 1);
                int target = 8*(t+1);
                while (__ldcg((const int*)ctr) < target) __nanosleep(20);
            }
            __syncthreads();
        }
    }
}

// ---------------- big GEMM: Z2 = A2 @ Wih2^T (single-pass fp16) ----------------
#define SETSZ (2*128*LDG2)
#define GCBYTES (128*LDC*4)             // 67584 — fp32 C tile in epilogue
#define GEMM_SMEM GCBYTES               // staging (49152 B) fits inside this

__global__ void __launch_bounds__(256,2) gemm_z2(){
    extern __shared__ char sm[];
    __half* buf = (__half*)sm;
    float* sC = (float*)sm;
    const int tid = threadIdx.x, wid = tid>>5;
    const int n0 = blockIdx.x*128;
    const int m0 = blockIdx.y*128;
    const int wm = (wid&3)*32, wn = (wid>>2)*64;

    wmma::fragment<wmma::accumulator,16,16,16,float> acc[2][4];
    #pragma unroll
    for (int i=0;i<2;i++)
        #pragma unroll
        for (int j=0;j<4;j++) wmma::fill_fragment(acc[i][j], 0.f);

    #pragma unroll
    for (int it=0; it<2; it++){
        int lin = tid + it*256; int r = lin>>2, seg = lin&3;
        *(uint4*)(buf + r*LDG2 + seg*8)            = *(const uint4*)(d_A2 + (size_t)(m0+r)*512 + seg*8);
        *(uint4*)(buf + 128*LDG2 + r*LDG2 + seg*8) = *(const uint4*)(d_Wih2 + (size_t)(n0+r)*512 + seg*8);
    }
    __syncthreads();

    for (int kc=0; kc<16; kc++){
        uint4 v[4];
        if (kc < 15){
            #pragma unroll
            for (int it=0; it<2; it++){
                int lin = tid + it*256; int r = lin>>2, seg = lin&3;
                size_t ka = (size_t)(m0+r)*512 + (kc+1)*32 + seg*8;
                size_t kw = (size_t)(n0+r)*512 + (kc+1)*32 + seg*8;
                v[it*2+0] = *(const uint4*)(d_A2 + ka);
                v[it*2+1] = *(const uint4*)(d_Wih2 + kw);
            }
        }
        {
            const __half* p = buf + (kc&1)*SETSZ;
            #pragma unroll
            for (int k16=0; k16<2; k16++){
                wmma::fragment<wmma::matrix_a,16,16,16,__half,wmma::row_major> fa[2];
                #pragma unroll
                for (int i=0;i<2;i++)
                    wmma::load_matrix_sync(fa[i], p + (wm+16*i)*LDG2 + k16*16, LDG2);
                #pragma unroll
                for (int j=0;j<4;j++){
                    wmma::fragment<wmma::matrix_b,16,16,16,__half,wmma::col_major> fb;
                    wmma::load_matrix_sync(fb, p + 128*LDG2 + (wn+16*j)*LDG2 + k16*16, LDG2);
                    #pragma unroll
                    for (int i=0;i<2;i++)
                        wmma::mma_sync(acc[i][j], fa[i], fb, acc[i][j]);
                }
            }
        }
        if (kc < 15){
            __half* q = buf + ((kc+1)&1)*SETSZ;
            #pragma unroll
            for (int it=0; it<2; it++){
                int lin = tid + it*256; int r = lin>>2, seg = lin&3;
                *(uint4*)(q + r*LDG2 + seg*8)            = v[it*2+0];
                *(uint4*)(q + 128*LDG2 + r*LDG2 + seg*8) = v[it*2+1];
            }
        }
        __syncthreads();
    }

    #pragma unroll
    for (int i=0;i<2;i++)
        #pragma unroll
        for (int j=0;j<4;j++)
            wmma::store_matrix_sync(sC + (wm+16*i)*LDC + wn + 16*j, acc[i][j],
                                    LDC, wmma::mem_row_major);
    __syncthreads();
    const int row = tid>>1, half = tid&1;
    __half2* zp = (__half2*)(d_Z2 + (size_t)(m0+row)*2048 + n0 + half*64);
    const float* cr = sC + row*LDC + half*64;
    #pragma unroll
    for (int j=0;j<32;j++)
        zp[j] = __floats2half2_rn(cr[2*j], cr[2*j+1]);
}

// ---------------- output projection ----------------
__global__ void proj_kernel(const float* __restrict__ Wout,
                            const float* __restrict__ bout,
                            const float* __restrict__ mask4,
                            float* __restrict__ out)
{
    int w = blockIdx.x*(blockDim.x>>5) + (threadIdx.x>>5);
    int lane = threadIdx.x & 31;
    if (w >= BB*TT) return;
    int b = w/TT, t = w%TT;
    float s = 0.f;
    #pragma unroll
    for (int j = lane; j < H2; j += 32)
        s += d_p2[t][b][j] * mask4[b*H2 + j] * Wout[j];
    #pragma unroll
    for (int o = 16; o > 0; o >>= 1) s += __shfl_xor_sync(0xffffffffu, s, o);
    if (lane == 0) out[b*TT + t] = s + bout[0] + d_m[b];
}

// ---------------- launcher ----------------
extern "C" void kernel_launch(void* const* d_in, const int* in_sizes, int n_in,
                              void* d_out, int out_size)
{
    const float* x0    = (const float*)d_in[0];
    const float* Wih1f = (const float*)d_in[1];
    const float* Whh1f = (const float*)d_in[2];
    const float* bih1f = (const float*)d_in[3];
    const float* bhh1f = (const float*)d_in[4];
    const float* Wih1b = (const float*)d_in[5];
    const float* Whh1b = (const float*)d_in[6];
    const float* bih1b = (const float*)d_in[7];
    const float* bhh1b = (const float*)d_in[8];
    const float* Wih2f = (const float*)d_in[9];
    const float* Whh2f = (const float*)d_in[10];
    const float* bih2f = (const float*)d_in[11];
    const float* bhh2f = (const float*)d_in[12];
    const float* Wih2b = (const float*)d_in[13];
    const float* Whh2b = (const float*)d_in[14];
    const float* bih2b = (const float*)d_in[15];
    const float* bhh2b = (const float*)d_in[16];
    const float* Wout  = (const float*)d_in[17];
    const float* bout  = (const float*)d_in[18];
    const float* mask1 = (const float*)d_in[19];
    const float* mask2 = (const float*)d_in[20];
    const float* mask3 = (const float*)d_in[21];
    const float* mask4 = (const float*)d_in[22];
    float* out = (float*)d_out;

    cudaFuncSetAttribute(lstm_persist<1>, cudaFuncAttributeMaxDynamicSharedMemorySize, PERSIST_SMEM);
    cudaFuncSetAttribute(lstm_persist<2>, cudaFuncAttributeMaxDynamicSharedMemorySize, PERSIST_SMEM);
    cudaFuncSetAttribute(gemm_z2, cudaFuncAttributeMaxDynamicSharedMemorySize, GEMM_SMEM);

    mean_kernel<<<(BB+255)/256, 256>>>(x0);
    zero_kernel<<<1, 32>>>();
    prep_weights<<<1024, 256>>>(Whh1f, Whh1b, Wih2f, Whh2f, Wih2b, Whh2b,
                                Wih1f, Wih1b,
                                bih1f, bhh1f, bih1b, bhh1b,
                                bih2f, bhh2f, bih2b, bhh2b);

    lstm_persist<1><<<dim3(8,8,2), 512, PERSIST_SMEM>>>(x0, mask1, mask2);
    gemm_z2<<<dim3(16,800), 256, GEMM_SMEM>>>();
    lstm_persist<2><<<dim3(8,8,2), 512, PERSIST_SMEM>>>(nullptr, mask3, nullptr);

    proj_kernel<<<(BB*TT+7)/8, 256>>>(Wout, bout, mask4, out);
}